// round 11
// baseline (speedup 1.0000x reference)
#include <cuda_runtime.h>
#include <cuda_bf16.h>
#include <cuda_fp16.h>
#include <mma.h>

using namespace nvcuda;

#define N_NODES 100000
#define N_EDGES 1600000
#define D 128
#define CAP 128          // per-node bucket capacity (max deg ~ Poisson(16) << 128)

#define GB_ROWS 128
#define GB_BLOCKS ((N_NODES + GB_ROWS - 1) / GB_ROWS)   // 782
#define LDH 136   // fp16 smem leading dim (pad 8)
#define LDC 132   // f32 staging leading dim (pad 4)

// ---------------- static device scratch ----------------
__device__ __half g_h[(size_t)N_NODES * D];      // h (then hn after fold), fp16
__device__ float g_dis[N_NODES];                 // deg^{-1/2}
__device__ int   g_cursor[N_NODES];              // zero at load; re-zeroed by agg
__device__ int   g_colbuf[(size_t)N_NODES * CAP];// bucketed CSR columns

__device__ __forceinline__ unsigned h2_to_u32(__half2 h) {
    return *reinterpret_cast<unsigned*>(&h);
}
__device__ __forceinline__ __half2 u32_to_h2(unsigned u) {
    return *reinterpret_cast<__half2*>(&u);
}

// ---------------- GEMM (wmma) + bucket scatter ----------------
// Scatter needs only zeroed cursors (no count/scan). Atomics drain under MMA.
__global__ void __launch_bounds__(256) k_gemm_scatter(const float* __restrict__ x,
                                                      const float* __restrict__ W,
                                                      const int* __restrict__ src,
                                                      const int* __restrict__ dst) {
    extern __shared__ __align__(16) char smraw[];
    __half* xh = (__half*)smraw;
    __half* wh = xh + 128 * LDH;
    float*  stage = (float*)smraw;

    // fire-and-forget bucket scatter: 8 edges/thread
    {
        int e0 = (blockIdx.x * 256 + threadIdx.x) * 8;
        if (e0 + 7 < N_EDGES) {
            int4 d0 = *(const int4*)(dst + e0);
            int4 d1 = *(const int4*)(dst + e0 + 4);
            int4 s0 = *(const int4*)(src + e0);
            int4 s1 = *(const int4*)(src + e0 + 4);
            int p0 = atomicAdd(&g_cursor[d0.x], 1);
            int p1 = atomicAdd(&g_cursor[d0.y], 1);
            int p2 = atomicAdd(&g_cursor[d0.z], 1);
            int p3 = atomicAdd(&g_cursor[d0.w], 1);
            int p4 = atomicAdd(&g_cursor[d1.x], 1);
            int p5 = atomicAdd(&g_cursor[d1.y], 1);
            int p6 = atomicAdd(&g_cursor[d1.z], 1);
            int p7 = atomicAdd(&g_cursor[d1.w], 1);
            if (p0 < CAP) g_colbuf[((size_t)d0.x << 7) + p0] = s0.x;
            if (p1 < CAP) g_colbuf[((size_t)d0.y << 7) + p1] = s0.y;
            if (p2 < CAP) g_colbuf[((size_t)d0.z << 7) + p2] = s0.z;
            if (p3 < CAP) g_colbuf[((size_t)d0.w << 7) + p3] = s0.w;
            if (p4 < CAP) g_colbuf[((size_t)d1.x << 7) + p4] = s1.x;
            if (p5 < CAP) g_colbuf[((size_t)d1.y << 7) + p5] = s1.y;
            if (p6 < CAP) g_colbuf[((size_t)d1.z << 7) + p6] = s1.z;
            if (p7 < CAP) g_colbuf[((size_t)d1.w << 7) + p7] = s1.w;
        } else {
            for (int i = 0; i < 8; i++) {
                int e = e0 + i;
                if (e < N_EDGES) {
                    int d = dst[e];
                    int p = atomicAdd(&g_cursor[d], 1);
                    if (p < CAP) g_colbuf[((size_t)d << 7) + p] = src[e];
                }
            }
        }
    }

    int row0 = blockIdx.x * GB_ROWS;

    // W -> fp16 smem
    {
        const float4* Wg = (const float4*)W;
        #pragma unroll
        for (int i = threadIdx.x; i < 128 * 32; i += 256) {
            int r = i >> 5, c4 = i & 31;
            float4 v = Wg[r * 32 + c4];
            uint2 st;
            st.x = h2_to_u32(__floats2half2_rn(v.x, v.y));
            st.y = h2_to_u32(__floats2half2_rn(v.z, v.w));
            *(uint2*)&wh[r * LDH + c4 * 4] = st;
        }
    }
    // x rows -> fp16 smem (zero-pad past N); NO dis folding here (done in k_fold)
    {
        const float4* xg = (const float4*)x;
        #pragma unroll
        for (int i = threadIdx.x; i < 128 * 32; i += 256) {
            int r = i >> 5, c4 = i & 31;
            int gr = row0 + r;
            float4 v = (gr < N_NODES) ? xg[(size_t)gr * 32 + c4]
                                      : make_float4(0.f, 0.f, 0.f, 0.f);
            uint2 st;
            st.x = h2_to_u32(__floats2half2_rn(v.x, v.y));
            st.y = h2_to_u32(__floats2half2_rn(v.z, v.w));
            *(uint2*)&xh[r * LDH + c4 * 4] = st;
        }
    }
    __syncthreads();

    int warp = threadIdx.x >> 5;

    wmma::fragment<wmma::accumulator, 16, 16, 16, float> acc[8];
    #pragma unroll
    for (int nt = 0; nt < 8; nt++) wmma::fill_fragment(acc[nt], 0.0f);

    #pragma unroll
    for (int kt = 0; kt < 8; kt++) {
        wmma::fragment<wmma::matrix_a, 16, 16, 16, __half, wmma::row_major> af;
        wmma::load_matrix_sync(af, xh + (warp * 16) * LDH + kt * 16, LDH);
        #pragma unroll
        for (int nt = 0; nt < 8; nt++) {
            wmma::fragment<wmma::matrix_b, 16, 16, 16, __half, wmma::row_major> bf;
            wmma::load_matrix_sync(bf, wh + (kt * 16) * LDH + nt * 16, LDH);
            wmma::mma_sync(acc[nt], af, bf, acc[nt]);
        }
    }

    __syncthreads();
    #pragma unroll
    for (int nt = 0; nt < 8; nt++)
        wmma::store_matrix_sync(stage + (warp * 16) * LDC + nt * 16, acc[nt],
                                LDC, wmma::mem_row_major);
    __syncthreads();

    uint2* hv = (uint2*)g_h;
    #pragma unroll
    for (int i = threadIdx.x; i < 128 * 32; i += 256) {
        int r = i >> 5, q = i & 31;
        int row = row0 + r;
        if (row < N_NODES) {
            float4 v = *(const float4*)&stage[r * LDC + q * 4];
            uint2 st;
            st.x = h2_to_u32(__floats2half2_rn(v.x, v.y));
            st.y = h2_to_u32(__floats2half2_rn(v.z, v.w));
            hv[(size_t)row * 32 + q] = st;
        }
    }
}

// ---------------- fold: hn = dis .* h ; also store dis ----------------
// One thread per uint2 element (3.2M). cursor[row] = deg (broadcast in warp).
__global__ void __launch_bounds__(256) k_fold() {
    int i = blockIdx.x * 256 + threadIdx.x;          // 0 .. N_NODES*32-1
    if (i >= N_NODES * 32) return;
    int row = i >> 5;
    int deg = __ldg(&g_cursor[row]);
    deg = min(deg, CAP);
    float dv = rsqrtf((float)(deg + 1));
    if ((i & 31) == 0) g_dis[row] = dv;

    uint2* hv = (uint2*)g_h;
    uint2 v = hv[i];
    float2 a0 = __half22float2(u32_to_h2(v.x));
    float2 a1 = __half22float2(u32_to_h2(v.y));
    uint2 st;
    st.x = h2_to_u32(__floats2half2_rn(a0.x * dv, a0.y * dv));
    st.y = h2_to_u32(__floats2half2_rn(a1.x * dv, a1.y * dv));
    hv[i] = st;
}

// one warp per node: acc = hn[i] + sum_s hn[s]; out = relu(di*acc + b).
// HADD2 tree over quads. Re-zeroes cursor for the next graph replay.
__global__ void __launch_bounds__(256) k_agg(const float* __restrict__ b,
                                             float* __restrict__ out) {
    int node = blockIdx.x * 8 + (threadIdx.x >> 5);
    int lane = threadIdx.x & 31;
    if (node >= N_NODES) return;

    const uint2* h2 = (const uint2*)g_h;
    float di = g_dis[node];
    int cnt = min(g_cursor[node], CAP);
    if (lane == 0) g_cursor[node] = 0;               // reset for next replay

    uint2 hv = h2[(size_t)node * 32 + lane];
    float2 f0 = __half22float2(u32_to_h2(hv.x));
    float2 f1 = __half22float2(u32_to_h2(hv.y));
    float4 acc;
    acc.x = f0.x; acc.y = f0.y; acc.z = f1.x; acc.w = f1.y;   // self term = hn[i]

    int beg = node << 7;   // CAP = 128

    for (int base = 0; base < cnt; base += 32) {
        int myi = base + lane;
        int sc = (myi < cnt) ? __ldg(&g_colbuf[beg + myi]) : 0;
        int m = min(32, cnt - base);
        int t = 0;
        for (; t + 3 < m; t += 4) {
            int s0 = __shfl_sync(0xffffffffu, sc, t);
            int s1 = __shfl_sync(0xffffffffu, sc, t + 1);
            int s2 = __shfl_sync(0xffffffffu, sc, t + 2);
            int s3 = __shfl_sync(0xffffffffu, sc, t + 3);
            uint2 v0 = __ldg(&h2[(size_t)s0 * 32 + lane]);
            uint2 v1 = __ldg(&h2[(size_t)s1 * 32 + lane]);
            uint2 v2 = __ldg(&h2[(size_t)s2 * 32 + lane]);
            uint2 v3 = __ldg(&h2[(size_t)s3 * 32 + lane]);
            __half2 p0 = __hadd2(u32_to_h2(v0.x), u32_to_h2(v1.x));
            __half2 p1 = __hadd2(u32_to_h2(v0.y), u32_to_h2(v1.y));
            __half2 q0 = __hadd2(u32_to_h2(v2.x), u32_to_h2(v3.x));
            __half2 q1 = __hadd2(u32_to_h2(v2.y), u32_to_h2(v3.y));
            __half2 r0 = __hadd2(p0, q0);
            __half2 r1 = __hadd2(p1, q1);
            float2 g0 = __half22float2(r0);
            float2 g1 = __half22float2(r1);
            acc.x += g0.x;
            acc.y += g0.y;
            acc.z += g1.x;
            acc.w += g1.y;
        }
        for (; t < m; t++) {
            int s0 = __shfl_sync(0xffffffffu, sc, t);
            uint2 v0 = __ldg(&h2[(size_t)s0 * 32 + lane]);
            float2 a0 = __half22float2(u32_to_h2(v0.x));
            float2 a1 = __half22float2(u32_to_h2(v0.y));
            acc.x += a0.x;
            acc.y += a0.y;
            acc.z += a1.x;
            acc.w += a1.y;
        }
    }

    float4 bv = __ldg(&((const float4*)b)[lane]);
    float4 o;
    o.x = fmaxf(fmaf(di, acc.x, bv.x), 0.f);
    o.y = fmaxf(fmaf(di, acc.y, bv.y), 0.f);
    o.z = fmaxf(fmaf(di, acc.z, bv.z), 0.f);
    o.w = fmaxf(fmaf(di, acc.w, bv.w), 0.f);
    ((float4*)out)[(size_t)node * 32 + lane] = o;
}

// ---------------- launch ----------------
extern "C" void kernel_launch(void* const* d_in, const int* in_sizes, int n_in,
                              void* d_out, int out_size) {
    const float* x   = (const float*)d_in[0];
    const int*   ei  = (const int*)d_in[1];
    const float* W   = (const float*)d_in[2];
    const float* b   = (const float*)d_in[3];
    float* out = (float*)d_out;

    const int* src = ei;
    const int* dst = ei + N_EDGES;

    const int SMEM = 2 * 128 * LDH * 2;   // 69632 bytes
    cudaFuncSetAttribute(k_gemm_scatter, cudaFuncAttributeMaxDynamicSharedMemorySize, SMEM);

    k_gemm_scatter<<<GB_BLOCKS, 256, SMEM>>>(x, W, src, dst);
    k_fold<<<(N_NODES * 32 + 255) / 256, 256>>>();
    k_agg<<<(N_NODES + 7) / 8, 256>>>(b, out);
}

// round 12
// speedup vs baseline: 1.9862x; 1.9862x over previous
#include <cuda_runtime.h>
#include <cuda_bf16.h>
#include <cuda_fp16.h>
#include <mma.h>

using namespace nvcuda;

#define N_NODES 100000
#define N_EDGES 1600000
#define D 128

#define GB_ROWS 128
#define GB_BLOCKS ((N_NODES + GB_ROWS - 1) / GB_ROWS)   // 782
#define LDH 136   // fp16 smem leading dim (pad 8)
#define LDC 132   // f32 staging leading dim (pad 4)

// ---------------- static device scratch ----------------
__device__ __half g_h[(size_t)N_NODES * D];  // hn = dis .* (x @ W), fp16
__device__ float g_dis[N_NODES];             // deg^{-1/2}
__device__ int   g_deg[N_NODES];             // zero at load; re-zeroed by scan
__device__ int   g_rowptr[N_NODES + 1];
__device__ int   g_cursor[N_NODES];
__device__ int   g_col[N_EDGES];             // compact CSR (6.4MB, L2-resident)
#define SCAN_B 1024
#define N_SCAN_BLOCKS ((N_NODES + SCAN_B - 1) / SCAN_B)   // 98
__device__ int   g_post[N_SCAN_BLOCKS];      // block-total posts (total+1); reset by gemm
__device__ int   g_arrive;                   // count-phase arrival ticket; reset by gemm

__device__ __forceinline__ unsigned h2_to_u32(__half2 h) {
    return *reinterpret_cast<unsigned*>(&h);
}
__device__ __forceinline__ __half2 u32_to_h2(unsigned u) {
    return *reinterpret_cast<__half2*>(&u);
}

// ---------------- fused count + scan (98 co-resident blocks) ----------------
// Phase A: all blocks count degrees (16 edges/thread, fire-and-forget REDG).
// Phase B: device-wide arrival barrier (threadfence + ticket; all 98 blocks
//          are co-resident in wave 1, so spinning is safe).
// Phase C: shfl block scan + cross-block prefix via g_post spin; writes
//          dis, rowptr, cursor; re-zeroes deg.
__global__ void __launch_bounds__(SCAN_B) k_count_scan(const int* __restrict__ dst) {
    int tid = threadIdx.x;
    int lane = tid & 31, wid = tid >> 5;

    // ---- Phase A: count ----
    {
        int e0 = (blockIdx.x * SCAN_B + tid) * 16;
        #pragma unroll
        for (int c = 0; c < 4; c++) {
            int e = e0 + c * 4;
            if (e + 3 < N_EDGES) {
                int4 d4 = *(const int4*)(dst + e);
                atomicAdd(&g_deg[d4.x], 1);
                atomicAdd(&g_deg[d4.y], 1);
                atomicAdd(&g_deg[d4.z], 1);
                atomicAdd(&g_deg[d4.w], 1);
            } else {
                for (int i = 0; i < 4; i++)
                    if (e + i < N_EDGES) atomicAdd(&g_deg[dst[e + i]], 1);
            }
        }
    }

    // ---- Phase B: global barrier over the 98 blocks ----
    __threadfence();          // make this thread's REDG results visible
    __syncthreads();          // all threads of block fenced
    if (tid == 0) atomicAdd(&g_arrive, 1);
    if (tid == 0) {
        volatile int* a = &g_arrive;
        while (*a < N_SCAN_BLOCKS) { }
    }
    __syncthreads();

    // ---- Phase C: scan ----
    __shared__ int wsum[32];
    __shared__ int s_off;
    int gid = blockIdx.x * SCAN_B + tid;
    int v = (gid < N_NODES) ? g_deg[gid] : 0;
    if (gid < N_NODES) {
        g_dis[gid] = rsqrtf((float)(v + 1));
        g_deg[gid] = 0;                        // clean slate for next replay
    }
    if (tid == 0) s_off = 0;

    int xv = v;
    #pragma unroll
    for (int off = 1; off < 32; off <<= 1) {
        int t = __shfl_up_sync(0xffffffffu, xv, off);
        if (lane >= off) xv += t;
    }
    if (lane == 31) wsum[wid] = xv;
    __syncthreads();
    if (wid == 0) {
        int s = wsum[lane];
        #pragma unroll
        for (int off = 1; off < 32; off <<= 1) {
            int t = __shfl_up_sync(0xffffffffu, s, off);
            if (lane >= off) s += t;
        }
        wsum[lane] = s;
    }
    __syncthreads();
    int incl = xv + (wid > 0 ? wsum[wid - 1] : 0);
    int btotal = wsum[31];

    if (tid == 0) {
        __threadfence();
        atomicExch(&g_post[blockIdx.x], btotal + 1);
    }
    if (tid < blockIdx.x) {
        volatile int* p = g_post + tid;
        int pv;
        while ((pv = *p) == 0) { }
        atomicAdd(&s_off, pv - 1);
    }
    __syncthreads();
    int off = s_off;

    if (gid < N_NODES) {
        int r = incl - v + off;
        g_rowptr[gid] = r;
        g_cursor[gid] = r;
    }
    if (blockIdx.x == 0 && tid == 0) g_rowptr[N_NODES] = N_EDGES;
}

// ---------------- GEMM (wmma, x pre-scaled by dis) + inline CSR scatter ----------------
__global__ void __launch_bounds__(256) k_gemm_scatter(const float* __restrict__ x,
                                                      const float* __restrict__ W,
                                                      const int* __restrict__ src,
                                                      const int* __restrict__ dst) {
    extern __shared__ __align__(16) char smraw[];
    __half* xh = (__half*)smraw;
    __half* wh = xh + 128 * LDH;
    float*  stage = (float*)smraw;

    // reset scan sync state for the next graph replay (ordered before next k_count_scan)
    if (blockIdx.x == 0) {
        if (threadIdx.x < N_SCAN_BLOCKS) g_post[threadIdx.x] = 0;
        if (threadIdx.x == 128) g_arrive = 0;
    }

    // fire-and-forget scatter: 8 edges/thread, drains under the MMA work
    {
        int e0 = (blockIdx.x * 256 + threadIdx.x) * 8;
        if (e0 + 7 < N_EDGES) {
            int4 d0 = *(const int4*)(dst + e0);
            int4 d1 = *(const int4*)(dst + e0 + 4);
            int4 s0 = *(const int4*)(src + e0);
            int4 s1 = *(const int4*)(src + e0 + 4);
            int p0 = atomicAdd(&g_cursor[d0.x], 1);
            int p1 = atomicAdd(&g_cursor[d0.y], 1);
            int p2 = atomicAdd(&g_cursor[d0.z], 1);
            int p3 = atomicAdd(&g_cursor[d0.w], 1);
            int p4 = atomicAdd(&g_cursor[d1.x], 1);
            int p5 = atomicAdd(&g_cursor[d1.y], 1);
            int p6 = atomicAdd(&g_cursor[d1.z], 1);
            int p7 = atomicAdd(&g_cursor[d1.w], 1);
            g_col[p0] = s0.x; g_col[p1] = s0.y; g_col[p2] = s0.z; g_col[p3] = s0.w;
            g_col[p4] = s1.x; g_col[p5] = s1.y; g_col[p6] = s1.z; g_col[p7] = s1.w;
        } else {
            for (int i = 0; i < 8; i++) {
                int e = e0 + i;
                if (e < N_EDGES) {
                    int p = atomicAdd(&g_cursor[dst[e]], 1);
                    g_col[p] = src[e];
                }
            }
        }
    }

    int row0 = blockIdx.x * GB_ROWS;

    // W -> fp16 smem
    {
        const float4* Wg = (const float4*)W;
        #pragma unroll
        for (int i = threadIdx.x; i < 128 * 32; i += 256) {
            int r = i >> 5, c4 = i & 31;
            float4 v = Wg[r * 32 + c4];
            uint2 st;
            st.x = h2_to_u32(__floats2half2_rn(v.x, v.y));
            st.y = h2_to_u32(__floats2half2_rn(v.z, v.w));
            *(uint2*)&wh[r * LDH + c4 * 4] = st;
        }
    }
    // x rows scaled by dis -> fp16 smem (zero-pad past N)
    {
        const float4* xg = (const float4*)x;
        #pragma unroll
        for (int i = threadIdx.x; i < 128 * 32; i += 256) {
            int r = i >> 5, c4 = i & 31;
            int gr = row0 + r;
            float dv = 0.f;
            float4 v = make_float4(0.f, 0.f, 0.f, 0.f);
            if (gr < N_NODES) {
                dv = __ldg(&g_dis[gr]);
                v = xg[(size_t)gr * 32 + c4];
            }
            uint2 st;
            st.x = h2_to_u32(__floats2half2_rn(v.x * dv, v.y * dv));
            st.y = h2_to_u32(__floats2half2_rn(v.z * dv, v.w * dv));
            *(uint2*)&xh[r * LDH + c4 * 4] = st;
        }
    }
    __syncthreads();

    int warp = threadIdx.x >> 5;

    wmma::fragment<wmma::accumulator, 16, 16, 16, float> acc[8];
    #pragma unroll
    for (int nt = 0; nt < 8; nt++) wmma::fill_fragment(acc[nt], 0.0f);

    #pragma unroll
    for (int kt = 0; kt < 8; kt++) {
        wmma::fragment<wmma::matrix_a, 16, 16, 16, __half, wmma::row_major> af;
        wmma::load_matrix_sync(af, xh + (warp * 16) * LDH + kt * 16, LDH);
        #pragma unroll
        for (int nt = 0; nt < 8; nt++) {
            wmma::fragment<wmma::matrix_b, 16, 16, 16, __half, wmma::row_major> bf;
            wmma::load_matrix_sync(bf, wh + (kt * 16) * LDH + nt * 16, LDH);
            wmma::mma_sync(acc[nt], af, bf, acc[nt]);
        }
    }

    __syncthreads();
    #pragma unroll
    for (int nt = 0; nt < 8; nt++)
        wmma::store_matrix_sync(stage + (warp * 16) * LDC + nt * 16, acc[nt],
                                LDC, wmma::mem_row_major);
    __syncthreads();

    uint2* hv = (uint2*)g_h;
    #pragma unroll
    for (int i = threadIdx.x; i < 128 * 32; i += 256) {
        int r = i >> 5, q = i & 31;
        int row = row0 + r;
        if (row < N_NODES) {
            float4 v = *(const float4*)&stage[r * LDC + q * 4];
            uint2 st;
            st.x = h2_to_u32(__floats2half2_rn(v.x, v.y));
            st.y = h2_to_u32(__floats2half2_rn(v.z, v.w));
            hv[(size_t)row * 32 + q] = st;
        }
    }
}

// one warp per node: acc = hn[i] + sum_s hn[s]; out = relu(di*acc + b).
// 4 edges/step combined via 2-level HADD2 tree, one fp32 add per quad.
__global__ void __launch_bounds__(256) k_agg(const float* __restrict__ b,
                                             float* __restrict__ out) {
    int node = blockIdx.x * 8 + (threadIdx.x >> 5);
    int lane = threadIdx.x & 31;
    if (node >= N_NODES) return;

    const uint2* h2 = (const uint2*)g_h;
    float di = g_dis[node];

    uint2 hv = h2[(size_t)node * 32 + lane];
    float2 f0 = __half22float2(u32_to_h2(hv.x));
    float2 f1 = __half22float2(u32_to_h2(hv.y));
    float4 acc;
    acc.x = f0.x; acc.y = f0.y; acc.z = f1.x; acc.w = f1.y;   // self term = hn[i]

    int beg = g_rowptr[node];
    int cnt = g_rowptr[node + 1] - beg;

    for (int base = 0; base < cnt; base += 32) {
        int myi = base + lane;
        int sc = (myi < cnt) ? __ldg(&g_col[beg + myi]) : 0;
        int m = min(32, cnt - base);
        int t = 0;
        for (; t + 3 < m; t += 4) {
            int s0 = __shfl_sync(0xffffffffu, sc, t);
            int s1 = __shfl_sync(0xffffffffu, sc, t + 1);
            int s2 = __shfl_sync(0xffffffffu, sc, t + 2);
            int s3 = __shfl_sync(0xffffffffu, sc, t + 3);
            uint2 v0 = __ldg(&h2[(size_t)s0 * 32 + lane]);
            uint2 v1 = __ldg(&h2[(size_t)s1 * 32 + lane]);
            uint2 v2 = __ldg(&h2[(size_t)s2 * 32 + lane]);
            uint2 v3 = __ldg(&h2[(size_t)s3 * 32 + lane]);
            __half2 p0 = __hadd2(u32_to_h2(v0.x), u32_to_h2(v1.x));
            __half2 p1 = __hadd2(u32_to_h2(v0.y), u32_to_h2(v1.y));
            __half2 q0 = __hadd2(u32_to_h2(v2.x), u32_to_h2(v3.x));
            __half2 q1 = __hadd2(u32_to_h2(v2.y), u32_to_h2(v3.y));
            __half2 r0 = __hadd2(p0, q0);
            __half2 r1 = __hadd2(p1, q1);
            float2 g0 = __half22float2(r0);
            float2 g1 = __half22float2(r1);
            acc.x += g0.x;
            acc.y += g0.y;
            acc.z += g1.x;
            acc.w += g1.y;
        }
        for (; t < m; t++) {
            int s0 = __shfl_sync(0xffffffffu, sc, t);
            uint2 v0 = __ldg(&h2[(size_t)s0 * 32 + lane]);
            float2 a0 = __half22float2(u32_to_h2(v0.x));
            float2 a1 = __half22float2(u32_to_h2(v0.y));
            acc.x += a0.x;
            acc.y += a0.y;
            acc.z += a1.x;
            acc.w += a1.y;
        }
    }

    float4 bv = __ldg(&((const float4*)b)[lane]);
    float4 o;
    o.x = fmaxf(fmaf(di, acc.x, bv.x), 0.f);
    o.y = fmaxf(fmaf(di, acc.y, bv.y), 0.f);
    o.z = fmaxf(fmaf(di, acc.z, bv.z), 0.f);
    o.w = fmaxf(fmaf(di, acc.w, bv.w), 0.f);
    ((float4*)out)[(size_t)node * 32 + lane] = o;
}

// ---------------- launch ----------------
extern "C" void kernel_launch(void* const* d_in, const int* in_sizes, int n_in,
                              void* d_out, int out_size) {
    const float* x   = (const float*)d_in[0];
    const int*   ei  = (const int*)d_in[1];
    const float* W   = (const float*)d_in[2];
    const float* b   = (const float*)d_in[3];
    float* out = (float*)d_out;

    const int* src = ei;
    const int* dst = ei + N_EDGES;

    const int SMEM = 2 * 128 * LDH * 2;   // 69632 bytes
    cudaFuncSetAttribute(k_gemm_scatter, cudaFuncAttributeMaxDynamicSharedMemorySize, SMEM);

    k_count_scan<<<N_SCAN_BLOCKS, SCAN_B>>>(dst);
    k_gemm_scatter<<<GB_BLOCKS, 256, SMEM>>>(x, W, src, dst);
    k_agg<<<(N_NODES + 7) / 8, 256>>>(b, out);
}

// round 13
// speedup vs baseline: 2.1514x; 1.0831x over previous
#include <cuda_runtime.h>
#include <cuda_bf16.h>
#include <cuda_fp16.h>
#include <mma.h>

using namespace nvcuda;

#define N_NODES 100000
#define N_EDGES 1600000
#define D 128

#define GB_ROWS 128
#define GB_BLOCKS ((N_NODES + GB_ROWS - 1) / GB_ROWS)   // 782
#define LDH 136   // fp16 smem leading dim (pad 8)
#define LDC 132   // f32 staging leading dim (pad 4)

// ---------------- static device scratch ----------------
// g_h has ONE EXTRA ROW (index N_NODES) that is never written: zero at module
// load, used as a harmless gather target for out-of-range edge slots.
__device__ __half g_h[(size_t)(N_NODES + 1) * D]; // hn = dis .* (x @ W), fp16
__device__ float g_dis[N_NODES];             // deg^{-1/2}
__device__ int   g_deg[N_NODES];             // zero at load; re-zeroed by scan
__device__ int   g_rowptr[N_NODES + 1];
__device__ int   g_cursor[N_NODES];
__device__ int   g_col[N_EDGES];             // compact CSR (6.4MB, L2-resident)
#define SCAN_B 1024
#define N_SCAN_BLOCKS ((N_NODES + SCAN_B - 1) / SCAN_B)   // 98
__device__ int   g_post[N_SCAN_BLOCKS];      // block-total posts (total+1); zeroed by k_count

__device__ __forceinline__ unsigned h2_to_u32(__half2 h) {
    return *reinterpret_cast<unsigned*>(&h);
}
__device__ __forceinline__ __half2 u32_to_h2(unsigned u) {
    return *reinterpret_cast<__half2*>(&u);
}

// ---------------- degree count (+ reset scan posts for this replay) ----------------
__global__ void __launch_bounds__(256) k_count(const int* __restrict__ dst) {
    int gtid = blockIdx.x * 256 + threadIdx.x;
    if (gtid < N_SCAN_BLOCKS) g_post[gtid] = 0;
    int e0 = gtid * 4;
    if (e0 + 3 < N_EDGES) {
        int4 d4 = *(const int4*)(dst + e0);
        atomicAdd(&g_deg[d4.x], 1);
        atomicAdd(&g_deg[d4.y], 1);
        atomicAdd(&g_deg[d4.z], 1);
        atomicAdd(&g_deg[d4.w], 1);
    } else {
        for (int i = 0; i < 4; i++)
            if (e0 + i < N_EDGES) atomicAdd(&g_deg[dst[e0 + i]], 1);
    }
}

// ---------------- fused single-kernel scan (98 co-resident blocks) ----------------
__global__ void __launch_bounds__(SCAN_B) k_scan() {
    __shared__ int wsum[32];
    __shared__ int s_off;
    int tid = threadIdx.x;
    int lane = tid & 31, wid = tid >> 5;
    int gid = blockIdx.x * SCAN_B + tid;
    int v = (gid < N_NODES) ? g_deg[gid] : 0;
    if (gid < N_NODES) {
        g_dis[gid] = rsqrtf((float)(v + 1));
        g_deg[gid] = 0;
    }
    if (tid == 0) s_off = 0;

    int xv = v;
    #pragma unroll
    for (int off = 1; off < 32; off <<= 1) {
        int t = __shfl_up_sync(0xffffffffu, xv, off);
        if (lane >= off) xv += t;
    }
    if (lane == 31) wsum[wid] = xv;
    __syncthreads();
    if (wid == 0) {
        int s = wsum[lane];
        #pragma unroll
        for (int off = 1; off < 32; off <<= 1) {
            int t = __shfl_up_sync(0xffffffffu, s, off);
            if (lane >= off) s += t;
        }
        wsum[lane] = s;
    }
    __syncthreads();
    int incl = xv + (wid > 0 ? wsum[wid - 1] : 0);
    int btotal = wsum[31];

    if (tid == 0) {
        __threadfence();
        atomicExch(&g_post[blockIdx.x], btotal + 1);
    }
    if (tid < blockIdx.x) {
        volatile int* p = g_post + tid;
        int pv;
        while ((pv = *p) == 0) { }
        atomicAdd(&s_off, pv - 1);
    }
    __syncthreads();
    int off = s_off;

    if (gid < N_NODES) {
        int r = incl - v + off;
        g_rowptr[gid] = r;
        g_cursor[gid] = r;
    }
    if (blockIdx.x == 0 && tid == 0) g_rowptr[N_NODES] = N_EDGES;
}

// ---------------- GEMM (wmma, x pre-scaled by dis) + inline CSR scatter ----------------
__global__ void __launch_bounds__(256) k_gemm_scatter(const float* __restrict__ x,
                                                      const float* __restrict__ W,
                                                      const int* __restrict__ src,
                                                      const int* __restrict__ dst) {
    extern __shared__ __align__(16) char smraw[];
    __half* xh = (__half*)smraw;
    __half* wh = xh + 128 * LDH;
    float*  stage = (float*)smraw;

    // fire-and-forget scatter: 8 edges/thread, drains under the MMA work
    {
        int e0 = (blockIdx.x * 256 + threadIdx.x) * 8;
        if (e0 + 7 < N_EDGES) {
            int4 d0 = *(const int4*)(dst + e0);
            int4 d1 = *(const int4*)(dst + e0 + 4);
            int4 s0 = *(const int4*)(src + e0);
            int4 s1 = *(const int4*)(src + e0 + 4);
            int p0 = atomicAdd(&g_cursor[d0.x], 1);
            int p1 = atomicAdd(&g_cursor[d0.y], 1);
            int p2 = atomicAdd(&g_cursor[d0.z], 1);
            int p3 = atomicAdd(&g_cursor[d0.w], 1);
            int p4 = atomicAdd(&g_cursor[d1.x], 1);
            int p5 = atomicAdd(&g_cursor[d1.y], 1);
            int p6 = atomicAdd(&g_cursor[d1.z], 1);
            int p7 = atomicAdd(&g_cursor[d1.w], 1);
            g_col[p0] = s0.x; g_col[p1] = s0.y; g_col[p2] = s0.z; g_col[p3] = s0.w;
            g_col[p4] = s1.x; g_col[p5] = s1.y; g_col[p6] = s1.z; g_col[p7] = s1.w;
        } else {
            for (int i = 0; i < 8; i++) {
                int e = e0 + i;
                if (e < N_EDGES) {
                    int p = atomicAdd(&g_cursor[dst[e]], 1);
                    g_col[p] = src[e];
                }
            }
        }
    }

    int row0 = blockIdx.x * GB_ROWS;

    // W -> fp16 smem
    {
        const float4* Wg = (const float4*)W;
        #pragma unroll
        for (int i = threadIdx.x; i < 128 * 32; i += 256) {
            int r = i >> 5, c4 = i & 31;
            float4 v = Wg[r * 32 + c4];
            uint2 st;
            st.x = h2_to_u32(__floats2half2_rn(v.x, v.y));
            st.y = h2_to_u32(__floats2half2_rn(v.z, v.w));
            *(uint2*)&wh[r * LDH + c4 * 4] = st;
        }
    }
    // x rows scaled by dis -> fp16 smem (zero-pad past N)
    {
        const float4* xg = (const float4*)x;
        #pragma unroll
        for (int i = threadIdx.x; i < 128 * 32; i += 256) {
            int r = i >> 5, c4 = i & 31;
            int gr = row0 + r;
            float dv = 0.f;
            float4 v = make_float4(0.f, 0.f, 0.f, 0.f);
            if (gr < N_NODES) {
                dv = __ldg(&g_dis[gr]);
                v = xg[(size_t)gr * 32 + c4];
            }
            uint2 st;
            st.x = h2_to_u32(__floats2half2_rn(v.x * dv, v.y * dv));
            st.y = h2_to_u32(__floats2half2_rn(v.z * dv, v.w * dv));
            *(uint2*)&xh[r * LDH + c4 * 4] = st;
        }
    }
    __syncthreads();

    int warp = threadIdx.x >> 5;

    wmma::fragment<wmma::accumulator, 16, 16, 16, float> acc[8];
    #pragma unroll
    for (int nt = 0; nt < 8; nt++) wmma::fill_fragment(acc[nt], 0.0f);

    #pragma unroll
    for (int kt = 0; kt < 8; kt++) {
        wmma::fragment<wmma::matrix_a, 16, 16, 16, __half, wmma::row_major> af;
        wmma::load_matrix_sync(af, xh + (warp * 16) * LDH + kt * 16, LDH);
        #pragma unroll
        for (int nt = 0; nt < 8; nt++) {
            wmma::fragment<wmma::matrix_b, 16, 16, 16, __half, wmma::row_major> bf;
            wmma::load_matrix_sync(bf, wh + (kt * 16) * LDH + nt * 16, LDH);
            wmma::mma_sync(acc[nt], af, bf, acc[nt]);
        }
    }

    __syncthreads();
    #pragma unroll
    for (int nt = 0; nt < 8; nt++)
        wmma::store_matrix_sync(stage + (warp * 16) * LDC + nt * 16, acc[nt],
                                LDC, wmma::mem_row_major);
    __syncthreads();

    uint2* hv = (uint2*)g_h;
    #pragma unroll
    for (int i = threadIdx.x; i < 128 * 32; i += 256) {
        int r = i >> 5, q = i & 31;
        int row = row0 + r;
        if (row < N_NODES) {
            float4 v = *(const float4*)&stage[r * LDC + q * 4];
            uint2 st;
            st.x = h2_to_u32(__floats2half2_rn(v.x, v.y));
            st.y = h2_to_u32(__floats2half2_rn(v.z, v.w));
            hv[(size_t)row * 32 + q] = st;
        }
    }
}

// ---------------- agg: 2 nodes per warp, 16 lanes each, uint4 (8 halves) per lane
// acc = hn[i] + sum_s hn[s]; out = relu(di*acc + b). Quad HADD2 tree.
// Out-of-range edge slots gather the permanent zero row (index N_NODES).
__global__ void __launch_bounds__(256) k_agg(const float* __restrict__ b,
                                             float* __restrict__ out) {
    int wg = threadIdx.x >> 5;
    int lane = threadIdx.x & 31;
    int half = lane >> 4;
    int sub = lane & 15;
    int node = (blockIdx.x * 8 + wg) * 2 + half;   // grid exactly covers 100000

    const uint4* h4 = (const uint4*)g_h;   // 16 uint4 (128 halves) per row
    float di = g_dis[node];
    int beg = g_rowptr[node];
    int cnt = g_rowptr[node + 1] - beg;
    int cntO = __shfl_xor_sync(0xffffffffu, cnt, 16);
    int cmax = max(cnt, cntO);
    int srcbase = half << 4;

    uint4 hv = h4[(size_t)node * 16 + sub];
    float2 e0 = __half22float2(u32_to_h2(hv.x));
    float2 e1 = __half22float2(u32_to_h2(hv.y));
    float2 e2 = __half22float2(u32_to_h2(hv.z));
    float2 e3 = __half22float2(u32_to_h2(hv.w));
    float4 acc0, acc1;
    acc0.x = e0.x; acc0.y = e0.y; acc0.z = e1.x; acc0.w = e1.y;
    acc1.x = e2.x; acc1.y = e2.y; acc1.z = e3.x; acc1.w = e3.y;

    for (int base = 0; base < cmax; base += 16) {
        int myi = base + sub;
        int sc = (myi < cnt) ? __ldg(&g_col[beg + myi]) : N_NODES;  // zero row
        int m = min(16, cmax - base);
        int t = 0;
        for (; t + 3 < m; t += 4) {
            int s0 = __shfl_sync(0xffffffffu, sc, srcbase + t);
            int s1 = __shfl_sync(0xffffffffu, sc, srcbase + t + 1);
            int s2 = __shfl_sync(0xffffffffu, sc, srcbase + t + 2);
            int s3 = __shfl_sync(0xffffffffu, sc, srcbase + t + 3);
            uint4 v0 = __ldg(&h4[(size_t)s0 * 16 + sub]);
            uint4 v1 = __ldg(&h4[(size_t)s1 * 16 + sub]);
            uint4 v2 = __ldg(&h4[(size_t)s2 * 16 + sub]);
            uint4 v3 = __ldg(&h4[(size_t)s3 * 16 + sub]);
            __half2 r0 = __hadd2(__hadd2(u32_to_h2(v0.x), u32_to_h2(v1.x)),
                                 __hadd2(u32_to_h2(v2.x), u32_to_h2(v3.x)));
            __half2 r1 = __hadd2(__hadd2(u32_to_h2(v0.y), u32_to_h2(v1.y)),
                                 __hadd2(u32_to_h2(v2.y), u32_to_h2(v3.y)));
            __half2 r2 = __hadd2(__hadd2(u32_to_h2(v0.z), u32_to_h2(v1.z)),
                                 __hadd2(u32_to_h2(v2.z), u32_to_h2(v3.z)));
            __half2 r3 = __hadd2(__hadd2(u32_to_h2(v0.w), u32_to_h2(v1.w)),
                                 __hadd2(u32_to_h2(v2.w), u32_to_h2(v3.w)));
            float2 g0 = __half22float2(r0);
            float2 g1 = __half22float2(r1);
            float2 g2 = __half22float2(r2);
            float2 g3 = __half22float2(r3);
            acc0.x += g0.x; acc0.y += g0.y; acc0.z += g1.x; acc0.w += g1.y;
            acc1.x += g2.x; acc1.y += g2.y; acc1.z += g3.x; acc1.w += g3.y;
        }
        for (; t < m; t++) {
            int s0 = __shfl_sync(0xffffffffu, sc, srcbase + t);
            uint4 v0 = __ldg(&h4[(size_t)s0 * 16 + sub]);
            float2 g0 = __half22float2(u32_to_h2(v0.x));
            float2 g1 = __half22float2(u32_to_h2(v0.y));
            float2 g2 = __half22float2(u32_to_h2(v0.z));
            float2 g3 = __half22float2(u32_to_h2(v0.w));
            acc0.x += g0.x; acc0.y += g0.y; acc0.z += g1.x; acc0.w += g1.y;
            acc1.x += g2.x; acc1.y += g2.y; acc1.z += g3.x; acc1.w += g3.y;
        }
    }

    const float4* b4 = (const float4*)b;
    float4 bv0 = __ldg(&b4[sub * 2]);
    float4 bv1 = __ldg(&b4[sub * 2 + 1]);
    float4 o0, o1;
    o0.x = fmaxf(fmaf(di, acc0.x, bv0.x), 0.f);
    o0.y = fmaxf(fmaf(di, acc0.y, bv0.y), 0.f);
    o0.z = fmaxf(fmaf(di, acc0.z, bv0.z), 0.f);
    o0.w = fmaxf(fmaf(di, acc0.w, bv0.w), 0.f);
    o1.x = fmaxf(fmaf(di, acc1.x, bv1.x), 0.f);
    o1.y = fmaxf(fmaf(di, acc1.y, bv1.y), 0.f);
    o1.z = fmaxf(fmaf(di, acc1.z, bv1.z), 0.f);
    o1.w = fmaxf(fmaf(di, acc1.w, bv1.w), 0.f);
    float4* o4 = (float4*)out;
    o4[(size_t)node * 32 + sub * 2]     = o0;
    o4[(size_t)node * 32 + sub * 2 + 1] = o1;
}

// ---------------- launch ----------------
extern "C" void kernel_launch(void* const* d_in, const int* in_sizes, int n_in,
                              void* d_out, int out_size) {
    const float* x   = (const float*)d_in[0];
    const int*   ei  = (const int*)d_in[1];
    const float* W   = (const float*)d_in[2];
    const float* b   = (const float*)d_in[3];
    float* out = (float*)d_out;

    const int* src = ei;
    const int* dst = ei + N_EDGES;

    const int SMEM = 2 * 128 * LDH * 2;   // 69632 bytes
    cudaFuncSetAttribute(k_gemm_scatter, cudaFuncAttributeMaxDynamicSharedMemorySize, SMEM);

    k_count<<<(N_EDGES / 4 + 255) / 256, 256>>>(dst);
    k_scan<<<N_SCAN_BLOCKS, SCAN_B>>>();
    k_gemm_scatter<<<GB_BLOCKS, 256, SMEM>>>(x, W, src, dst);
    k_agg<<<N_NODES / 16, 256>>>(b, out);   // 6250 blocks x 8 warps x 2 nodes
}